// round 1
// baseline (speedup 1.0000x reference)
#include <cuda_runtime.h>
#include <math.h>

#define BATCH 2
#define C1 256
#define NPIX 4096
#define INTER 32
#define KDIM 768
#define NTILES 32          // 4096 / 128
#define NPAIRS 528         // NTILES*(NTILES+1)/2

// ---------------- scratch (static device globals; no allocation allowed) ---
__device__ float d_p3[BATCH * C1 * NPIX];
__device__ float d_p5[BATCH * C1 * NPIX];
__device__ float d_Q[(size_t)BATCH * NPIX * KDIM];
__device__ float d_g[BATCH * NPIX * INTER];
__device__ float d_f[(size_t)BATCH * NPIX * NPIX];     // 134 MB
__device__ float d_s[BATCH * 3 * C1];
__device__ float d_sqrtV[BATCH * 3];
__device__ float d_rowmax[BATCH * NPIX];
__device__ float d_rowsum[BATCH * NPIX];
__device__ float d_ypart[4 * BATCH * NPIX * INTER];

// ---------------- K1: 3x3 & 5x5 avg pool (count_include_pad) + plane sums --
__global__ void pool_kernel(const float* __restrict__ x) {
    __shared__ float sm[64 * 64];
    __shared__ float red[3][256];
    int plane = blockIdx.x;                  // b*C1 + c
    const float* xp = x + (size_t)plane * NPIX;
    int t = threadIdx.x;
    float sx = 0.f;
    #pragma unroll
    for (int j = 0; j < 16; j++) {
        float v = xp[t + 256 * j];
        sm[t + 256 * j] = v;
        sx += v;
    }
    __syncthreads();
    float s3sum = 0.f, s5sum = 0.f;
    #pragma unroll 1
    for (int j = 0; j < 16; j++) {
        int idx = t + 256 * j;
        int py = idx >> 6, px = idx & 63;
        float s5 = 0.f, s3 = 0.f;
        #pragma unroll
        for (int dy = -2; dy <= 2; dy++) {
            int yy = py + dy;
            if (yy < 0 || yy > 63) continue;
            #pragma unroll
            for (int dx = -2; dx <= 2; dx++) {
                int xx = px + dx;
                if (xx < 0 || xx > 63) continue;
                float v = sm[yy * 64 + xx];
                s5 += v;
                if (dy >= -1 && dy <= 1 && dx >= -1 && dx <= 1) s3 += v;
            }
        }
        float v3 = s3 * (1.f / 9.f), v5 = s5 * (1.f / 25.f);
        d_p3[(size_t)plane * NPIX + idx] = v3;
        d_p5[(size_t)plane * NPIX + idx] = v5;
        s3sum += v3; s5sum += v5;
    }
    red[0][t] = sx; red[1][t] = s3sum; red[2][t] = s5sum;
    __syncthreads();
    for (int off = 128; off > 0; off >>= 1) {
        if (t < off) {
            red[0][t] += red[0][t + off];
            red[1][t] += red[1][t + off];
            red[2][t] += red[2][t + off];
        }
        __syncthreads();
    }
    if (t == 0) {
        int b = plane / C1, c = plane % C1;
        d_s[(b * 3 + 0) * C1 + c] = red[0][0];
        d_s[(b * 3 + 1) * C1 + c] = red[1][0];
        d_s[(b * 3 + 2) * C1 + c] = red[2][0];
    }
}

// ---------------- K2: v -> gating softmax V, store sqrt(V) ----------------
__global__ void vcalc_kernel(const float* __restrict__ W1, const float* __restrict__ W2) {
    __shared__ float vsh[BATCH][3];
    int t = threadIdx.x;
    int w = t >> 5, lane = t & 31;
    if (w < 6) {
        int b = w / 3, i = w % 3;
        float acc = 0.f;
        for (int c = lane; c < C1; c += 32) {
            float sv = d_s[(b * 3 + i) * C1 + c];
            acc += sv * sv;
        }
        #pragma unroll
        for (int off = 16; off > 0; off >>= 1)
            acc += __shfl_down_sync(0xffffffffu, acc, off);
        if (lane == 0) vsh[b][i] = acc * (1.f / ((float)NPIX * (float)NPIX));
    }
    __syncthreads();
    if (t < BATCH) {
        int b = t;
        float u[16];
        #pragma unroll
        for (int k = 0; k < 16; k++) {
            float a = 0.f;
            #pragma unroll
            for (int j = 0; j < 3; j++) a += vsh[b][j] * W1[k * 3 + j];
            u[k] = a;
        }
        float wv[3];
        float mx = -1e30f;
        #pragma unroll
        for (int i = 0; i < 3; i++) {
            float a = 0.f;
            #pragma unroll
            for (int k = 0; k < 16; k++) a += u[k] * W2[i * 16 + k];
            wv[i] = a;
            mx = fmaxf(mx, a);
        }
        float den = 0.f;
        #pragma unroll
        for (int i = 0; i < 3; i++) { wv[i] = expf(wv[i] - mx); den += wv[i]; }
        #pragma unroll
        for (int i = 0; i < 3; i++) d_sqrtV[b * 3 + i] = sqrtf(wv[i] / den);
    }
}

// ---------------- K3: build Q[b][n][k] = sqrtV * src[c][n] (transpose) -----
__global__ void buildq_kernel(const float* __restrict__ x) {
    __shared__ float tile[32][33];
    int n0 = blockIdx.x * 32;
    int by = blockIdx.y;                   // 0..23 -> k0 = by*32
    int b = blockIdx.z;
    int arr = by >> 3;                     // 0:x 1:p3 2:p5
    int c0 = (by & 7) * 32;
    const float* src = (arr == 0) ? x : (arr == 1) ? d_p3 : d_p5;
    float scale = d_sqrtV[b * 3 + arr];
    int tx = threadIdx.x, ty = threadIdx.y; // (32, 8)
    #pragma unroll
    for (int r = 0; r < 4; r++) {
        int cy = ty + 8 * r;
        tile[cy][tx] = src[((size_t)(b * C1 + c0 + cy)) * NPIX + n0 + tx];
    }
    __syncthreads();
    int k0 = by * 32;
    #pragma unroll
    for (int r = 0; r < 4; r++) {
        int rowl = ty + 8 * r;
        d_Q[((size_t)(b * NPIX + n0 + rowl)) * KDIM + k0 + tx] = tile[tx][rowl] * scale;
    }
}

// ---------------- K4: g_x[b][m][i] = sum_c Wg[i][c] x[b][c][m] ------------
__global__ void gx_kernel(const float* __restrict__ x, const float* __restrict__ Wg) {
    __shared__ float wg[INTER * C1];       // 32 KB
    int t = threadIdx.x;
    for (int j = t; j < INTER * C1; j += 256) wg[j] = Wg[j];
    __syncthreads();
    int b = blockIdx.y;
    int m = blockIdx.x * 256 + t;
    float acc[INTER];
    #pragma unroll
    for (int i = 0; i < INTER; i++) acc[i] = 0.f;
    const float* xp = x + (size_t)b * C1 * NPIX + m;
    for (int c = 0; c < C1; c++) {
        float xv = xp[(size_t)c * NPIX];
        #pragma unroll
        for (int i = 0; i < INTER; i++)
            acc[i] += wg[i * C1 + c] * xv;
    }
    float* gp = d_g + ((size_t)(b * NPIX + m)) * INTER;
    #pragma unroll
    for (int i = 0; i < INTER; i++) gp[i] = acc[i];
}

// ---------------- K5: f = Q Q^T, symmetric-pair tiles, 128x128x8 SGEMM -----
#define LDA 132
__global__ __launch_bounds__(256, 2) void gemm1_kernel() {
    __shared__ float As[8 * LDA];
    __shared__ float Bs[8 * LDA];
    int p = blockIdx.x;
    int b = blockIdx.y;
    int bi = 0;
    while (p >= NTILES - bi) { p -= NTILES - bi; bi++; }
    int bj = bi + p;
    int n0 = bi * 128, m0 = bj * 128;
    const float* Qb = d_Q + (size_t)b * NPIX * KDIM;
    int t = threadIdx.x;
    int lrow = t >> 1, lk = (t & 1) * 4;
    const float* aload = Qb + (size_t)(n0 + lrow) * KDIM + lk;
    const float* bload = Qb + (size_t)(m0 + lrow) * KDIM + lk;
    int ty = t >> 4, tx = t & 15;
    float acc[8][8] = {};
    for (int kt = 0; kt < KDIM; kt += 8) {
        float4 av = *(const float4*)(aload + kt);
        float4 bv = *(const float4*)(bload + kt);
        As[(lk + 0) * LDA + lrow] = av.x;
        As[(lk + 1) * LDA + lrow] = av.y;
        As[(lk + 2) * LDA + lrow] = av.z;
        As[(lk + 3) * LDA + lrow] = av.w;
        Bs[(lk + 0) * LDA + lrow] = bv.x;
        Bs[(lk + 1) * LDA + lrow] = bv.y;
        Bs[(lk + 2) * LDA + lrow] = bv.z;
        Bs[(lk + 3) * LDA + lrow] = bv.w;
        __syncthreads();
        #pragma unroll
        for (int kk = 0; kk < 8; kk++) {
            float a[8], bb[8];
            *(float4*)(a)      = *(const float4*)(As + kk * LDA + ty * 8);
            *(float4*)(a + 4)  = *(const float4*)(As + kk * LDA + ty * 8 + 4);
            *(float4*)(bb)     = *(const float4*)(Bs + kk * LDA + tx * 8);
            *(float4*)(bb + 4) = *(const float4*)(Bs + kk * LDA + tx * 8 + 4);
            #pragma unroll
            for (int r = 0; r < 8; r++)
                #pragma unroll
                for (int cc = 0; cc < 8; cc++)
                    acc[r][cc] += a[r] * bb[cc];
        }
        __syncthreads();
    }
    float* fb = d_f + (size_t)b * NPIX * NPIX;
    #pragma unroll
    for (int r = 0; r < 8; r++) {
        float* dst = fb + (size_t)(n0 + ty * 8 + r) * NPIX + m0 + tx * 8;
        *(float4*)(dst)     = make_float4(acc[r][0], acc[r][1], acc[r][2], acc[r][3]);
        *(float4*)(dst + 4) = make_float4(acc[r][4], acc[r][5], acc[r][6], acc[r][7]);
    }
    if (bi != bj) {
        #pragma unroll
        for (int cc = 0; cc < 8; cc++) {
            float* dst = fb + (size_t)(m0 + tx * 8 + cc) * NPIX + n0 + ty * 8;
            *(float4*)(dst)     = make_float4(acc[0][cc], acc[1][cc], acc[2][cc], acc[3][cc]);
            *(float4*)(dst + 4) = make_float4(acc[4][cc], acc[5][cc], acc[6][cc], acc[7][cc]);
        }
    }
}

// ---------------- K6: per-row online max + sum(exp) -----------------------
__global__ void stats_kernel() {
    __shared__ float sm_m[8], sm_s[8];
    int b = blockIdx.y;
    int n = blockIdx.x;
    const float* row = d_f + ((size_t)(b * NPIX + n)) * NPIX;
    int t = threadIdx.x;
    float m = -1e30f, ssum = 0.f;
    for (int j = t; j < NPIX; j += 256) {
        float v = row[j];
        if (v > m) { ssum = ssum * __expf(m - v) + 1.f; m = v; }
        else ssum += __expf(v - m);
    }
    #pragma unroll
    for (int off = 16; off > 0; off >>= 1) {
        float m2 = __shfl_down_sync(0xffffffffu, m, off);
        float s2 = __shfl_down_sync(0xffffffffu, ssum, off);
        float mm = fmaxf(m, m2);
        ssum = ssum * __expf(m - mm) + s2 * __expf(m2 - mm);
        m = mm;
    }
    int w = t >> 5, lane = t & 31;
    if (lane == 0) { sm_m[w] = m; sm_s[w] = ssum; }
    __syncthreads();
    if (t == 0) {
        m = sm_m[0]; ssum = sm_s[0];
        #pragma unroll
        for (int i = 1; i < 8; i++) {
            float m2 = sm_m[i], s2 = sm_s[i];
            float mm = fmaxf(m, m2);
            ssum = ssum * __expf(m - mm) + s2 * __expf(m2 - mm);
            m = mm;
        }
        d_rowmax[b * NPIX + n] = m;
        d_rowsum[b * NPIX + n] = ssum;
    }
}

// ---------------- K7: y_part = exp(f - rowmax) @ g_x (K split x4) ---------
__global__ void gemm2_kernel() {
    __shared__ float Ps[64 * 64];          // 16 KB
    __shared__ float Gs[64 * 32];          // 8 KB
    int b = blockIdx.z;
    int ks = blockIdx.y;
    int n0 = blockIdx.x * 64;
    int t = threadIdx.x;
    int i = t & 31, rg = t >> 5;           // rg: 0..7 (rows rg*8 .. rg*8+7)
    float acc[8] = {};
    const float* fb = d_f + (size_t)b * NPIX * NPIX;
    const float* gb = d_g + (size_t)b * NPIX * INTER;
    // row index for load slot j is fixed: (t>>6) + 4*j
    float rmax[16];
    #pragma unroll
    for (int j = 0; j < 16; j++)
        rmax[j] = d_rowmax[b * NPIX + n0 + (t >> 6) + 4 * j];
    for (int mc = ks * 1024; mc < ks * 1024 + 1024; mc += 64) {
        #pragma unroll
        for (int j = 0; j < 16; j++) {
            int idx = t + 256 * j;
            int row = (t >> 6) + 4 * j, m = idx & 63;
            float fv = fb[(size_t)(n0 + row) * NPIX + mc + m];
            Ps[idx] = __expf(fv - rmax[j]);
        }
        #pragma unroll
        for (int j = 0; j < 8; j++) {
            int idx = t + 256 * j;
            Gs[idx] = gb[(size_t)mc * INTER + idx];
        }
        __syncthreads();
        #pragma unroll 2
        for (int m = 0; m < 64; m += 4) {
            float g0 = Gs[(m + 0) * 32 + i];
            float g1 = Gs[(m + 1) * 32 + i];
            float g2 = Gs[(m + 2) * 32 + i];
            float g3 = Gs[(m + 3) * 32 + i];
            #pragma unroll
            for (int r = 0; r < 8; r++) {
                float4 pv = *(const float4*)(Ps + (rg * 8 + r) * 64 + m);
                acc[r] += pv.x * g0 + pv.y * g1 + pv.z * g2 + pv.w * g3;
            }
        }
        __syncthreads();
    }
    #pragma unroll
    for (int r = 0; r < 8; r++)
        d_ypart[(((size_t)ks * BATCH + b) * NPIX + n0 + rg * 8 + r) * INTER + i] = acc[r];
}

// ---------------- K8: z = Ww @ (sum ypart / rowsum) + x --------------------
__global__ void zfinal_kernel(const float* __restrict__ x, const float* __restrict__ Ww,
                              float* __restrict__ z) {
    __shared__ float Wws[C1 * INTER];      // 32 KB
    __shared__ float yt[64 * 33];
    int t = threadIdx.x;
    for (int j = t; j < C1 * INTER; j += 256) Wws[j] = Ww[j];
    int b = blockIdx.y;
    int hw0 = blockIdx.x * 64;
    #pragma unroll
    for (int j = 0; j < 8; j++) {
        int idx = t + 256 * j;             // 2048 = 64*32
        int hwl = idx >> 5, i = idx & 31;
        int n = hw0 + hwl;
        float a = 0.f;
        #pragma unroll
        for (int ksp = 0; ksp < 4; ksp++)
            a += d_ypart[(((size_t)ksp * BATCH + b) * NPIX + n) * INTER + i];
        yt[hwl * 33 + i] = a / d_rowsum[b * NPIX + n];
    }
    __syncthreads();
    int hwl = t & 63, c0 = t >> 6;
    for (int c = c0; c < C1; c += 4) {
        float a = 0.f;
        #pragma unroll
        for (int i = 0; i < INTER; i++)
            a += Wws[c * INTER + i] * yt[hwl * 33 + i];
        size_t off = ((size_t)(b * C1 + c)) * NPIX + hw0 + hwl;
        z[off] = a + x[off];
    }
}

// ---------------- launch ---------------------------------------------------
extern "C" void kernel_launch(void* const* d_in, const int* in_sizes, int n_in,
                              void* d_out, int out_size) {
    const float* x  = (const float*)d_in[0];
    const float* Wg = (const float*)d_in[1];
    const float* Ww = (const float*)d_in[2];
    const float* W1 = (const float*)d_in[3];
    const float* W2 = (const float*)d_in[4];
    float* z = (float*)d_out;

    pool_kernel<<<BATCH * C1, 256>>>(x);
    vcalc_kernel<<<1, 192>>>(W1, W2);
    buildq_kernel<<<dim3(128, 24, BATCH), dim3(32, 8)>>>(x);
    gx_kernel<<<dim3(16, BATCH), 256>>>(x, Wg);
    gemm1_kernel<<<dim3(NPAIRS, BATCH), 256>>>();
    stats_kernel<<<dim3(NPIX, BATCH), 256>>>();
    gemm2_kernel<<<dim3(64, 4, BATCH), 256>>>();
    zfinal_kernel<<<dim3(64, BATCH), 256>>>(x, Ww, z);
}

// round 4
// speedup vs baseline: 1.8132x; 1.8132x over previous
#include <cuda_runtime.h>
#include <cuda_bf16.h>
#include <math.h>
#include <stdint.h>

#define BATCH 2
#define C1 256
#define NPIX 4096
#define INTER 32
#define KDIM 768
#define NTILES 32          // 4096 / 128
#define NPAIRS 528         // NTILES*(NTILES+1)/2
#define NCHUNK 24          // 768 / 32

// ---------------- scratch ---------------------------------------------------
__device__ float d_p3[BATCH * C1 * NPIX];
__device__ float d_p5[BATCH * C1 * NPIX];
__device__ __nv_bfloat16 d_Qhi[(size_t)BATCH * NPIX * KDIM];
__device__ __nv_bfloat16 d_Qlo[(size_t)BATCH * NPIX * KDIM];
__device__ float d_g[BATCH * NPIX * INTER];
__device__ float d_f[(size_t)BATCH * NPIX * NPIX];     // 134 MB
__device__ float d_s[BATCH * 3 * C1];
__device__ float d_sqrtV[BATCH * 3];
__device__ float d_rowmax[BATCH * NPIX];
__device__ float d_rowsum[BATCH * NPIX];
__device__ float d_ypart[4 * BATCH * NPIX * INTER];

// ---------------- helpers ----------------------------------------------------
__device__ __forceinline__ uint32_t smem_u32(const void* p) {
    uint32_t a;
    asm("{ .reg .u64 t; cvta.to.shared.u64 t, %1; cvt.u32.u64 %0, t; }" : "=r"(a) : "l"(p));
    return a;
}
#define LDSM4(r, addr) \
    asm volatile("ldmatrix.sync.aligned.m8n8.x4.shared.b16 {%0,%1,%2,%3}, [%4];" \
        : "=r"((r)[0]), "=r"((r)[1]), "=r"((r)[2]), "=r"((r)[3]) : "r"(addr))
#define MMA16816(c, a, b) \
    asm volatile("mma.sync.aligned.m16n8k16.row.col.f32.bf16.bf16.f32 " \
        "{%0,%1,%2,%3}, {%4,%5,%6,%7}, {%8,%9}, {%0,%1,%2,%3};" \
        : "+f"((c)[0]), "+f"((c)[1]), "+f"((c)[2]), "+f"((c)[3]) \
        : "r"((a)[0]), "r"((a)[1]), "r"((a)[2]), "r"((a)[3]), \
          "r"((b)[0]), "r"((b)[1]))
#define CPASYNC16(saddr, gptr) \
    asm volatile("cp.async.cg.shared.global [%0], [%1], 16;" :: "r"(saddr), "l"(gptr) : "memory")
#define CPCOMMIT() asm volatile("cp.async.commit_group;" ::: "memory")
#define CPWAIT1()  asm volatile("cp.async.wait_group 1;" ::: "memory")

// ---------------- K1: 3x3 & 5x5 avg pool + plane sums -----------------------
__global__ void pool_kernel(const float* __restrict__ x) {
    __shared__ float sm[64 * 64];
    __shared__ float red[3][256];
    int plane = blockIdx.x;
    const float* xp = x + (size_t)plane * NPIX;
    int t = threadIdx.x;
    float sx = 0.f;
    #pragma unroll
    for (int j = 0; j < 16; j++) {
        float v = xp[t + 256 * j];
        sm[t + 256 * j] = v;
        sx += v;
    }
    __syncthreads();
    float s3sum = 0.f, s5sum = 0.f;
    #pragma unroll 1
    for (int j = 0; j < 16; j++) {
        int idx = t + 256 * j;
        int py = idx >> 6, px = idx & 63;
        float s5 = 0.f, s3 = 0.f;
        #pragma unroll
        for (int dy = -2; dy <= 2; dy++) {
            int yy = py + dy;
            if (yy < 0 || yy > 63) continue;
            #pragma unroll
            for (int dx = -2; dx <= 2; dx++) {
                int xx = px + dx;
                if (xx < 0 || xx > 63) continue;
                float v = sm[yy * 64 + xx];
                s5 += v;
                if (dy >= -1 && dy <= 1 && dx >= -1 && dx <= 1) s3 += v;
            }
        }
        float v3 = s3 * (1.f / 9.f), v5 = s5 * (1.f / 25.f);
        d_p3[(size_t)plane * NPIX + idx] = v3;
        d_p5[(size_t)plane * NPIX + idx] = v5;
        s3sum += v3; s5sum += v5;
    }
    red[0][t] = sx; red[1][t] = s3sum; red[2][t] = s5sum;
    __syncthreads();
    for (int off = 128; off > 0; off >>= 1) {
        if (t < off) {
            red[0][t] += red[0][t + off];
            red[1][t] += red[1][t + off];
            red[2][t] += red[2][t + off];
        }
        __syncthreads();
    }
    if (t == 0) {
        int b = plane / C1, c = plane % C1;
        d_s[(b * 3 + 0) * C1 + c] = red[0][0];
        d_s[(b * 3 + 1) * C1 + c] = red[1][0];
        d_s[(b * 3 + 2) * C1 + c] = red[2][0];
    }
}

// ---------------- K2: gating softmax V, store sqrt(V) -----------------------
__global__ void vcalc_kernel(const float* __restrict__ W1, const float* __restrict__ W2) {
    __shared__ float vsh[BATCH][3];
    int t = threadIdx.x;
    int w = t >> 5, lane = t & 31;
    if (w < 6) {
        int b = w / 3, i = w % 3;
        float acc = 0.f;
        for (int c = lane; c < C1; c += 32) {
            float sv = d_s[(b * 3 + i) * C1 + c];
            acc += sv * sv;
        }
        #pragma unroll
        for (int off = 16; off > 0; off >>= 1)
            acc += __shfl_down_sync(0xffffffffu, acc, off);
        if (lane == 0) vsh[b][i] = acc * (1.f / ((float)NPIX * (float)NPIX));
    }
    __syncthreads();
    if (t < BATCH) {
        int b = t;
        float u[16];
        #pragma unroll
        for (int k = 0; k < 16; k++) {
            float a = 0.f;
            #pragma unroll
            for (int j = 0; j < 3; j++) a += vsh[b][j] * W1[k * 3 + j];
            u[k] = a;
        }
        float wv[3];
        float mx = -1e30f;
        #pragma unroll
        for (int i = 0; i < 3; i++) {
            float a = 0.f;
            #pragma unroll
            for (int k = 0; k < 16; k++) a += u[k] * W2[i * 16 + k];
            wv[i] = a;
            mx = fmaxf(mx, a);
        }
        float den = 0.f;
        #pragma unroll
        for (int i = 0; i < 3; i++) { wv[i] = expf(wv[i] - mx); den += wv[i]; }
        #pragma unroll
        for (int i = 0; i < 3; i++) d_sqrtV[b * 3 + i] = sqrtf(wv[i] / den);
    }
}

// ---------------- K3: build Qhi/Qlo bf16 (transpose + scale + split) --------
__global__ void buildq_kernel(const float* __restrict__ x) {
    __shared__ float tile[32][33];
    int n0 = blockIdx.x * 32;
    int by = blockIdx.y;                   // 0..23 -> k0 = by*32
    int b = blockIdx.z;
    int arr = by >> 3;                     // 0:x 1:p3 2:p5
    int c0 = (by & 7) * 32;
    const float* src = (arr == 0) ? x : (arr == 1) ? d_p3 : d_p5;
    float scale = d_sqrtV[b * 3 + arr];
    int tx = threadIdx.x, ty = threadIdx.y; // (32, 8)
    #pragma unroll
    for (int r = 0; r < 4; r++) {
        int cy = ty + 8 * r;
        tile[cy][tx] = src[((size_t)(b * C1 + c0 + cy)) * NPIX + n0 + tx];
    }
    __syncthreads();
    int k0 = by * 32;
    #pragma unroll
    for (int r = 0; r < 4; r++) {
        int rowl = ty + 8 * r;
        float v = tile[tx][rowl] * scale;
        __nv_bfloat16 hi = __float2bfloat16(v);
        __nv_bfloat16 lo = __float2bfloat16(v - __bfloat162float(hi));
        size_t off = ((size_t)(b * NPIX + n0 + rowl)) * KDIM + k0 + tx;
        d_Qhi[off] = hi;
        d_Qlo[off] = lo;
    }
}

// ---------------- K4: g_x[b][m][i] = sum_c Wg[i][c] x[b][c][m] --------------
__global__ void gx_kernel(const float* __restrict__ x, const float* __restrict__ Wg) {
    __shared__ float wgs[INTER * C1];      // 32 KB (reused as reduction buffer)
    int t = threadIdx.x;
    for (int j = t; j < INTER * C1; j += 256) wgs[j] = Wg[j];
    __syncthreads();
    int b = blockIdx.y;
    int p = t & 127, ch = t >> 7;          // 2 chunks of 128 channels
    int m = blockIdx.x * 128 + p;
    float acc[INTER];
    #pragma unroll
    for (int i = 0; i < INTER; i++) acc[i] = 0.f;
    const float* xp = x + (size_t)b * C1 * NPIX + (size_t)(ch * 128) * NPIX + m;
    for (int c = 0; c < 128; c++) {
        float xv = xp[(size_t)c * NPIX];
        int cc = ch * 128 + c;
        #pragma unroll
        for (int i = 0; i < INTER; i++)
            acc[i] += wgs[i * C1 + cc] * xv;
    }
    __syncthreads();                       // all reads of wgs done; reuse as red buf
    if (ch == 1) {
        #pragma unroll
        for (int i = 0; i < INTER; i++) wgs[i * 128 + p] = acc[i];
    }
    __syncthreads();
    if (ch == 0) {
        float* gp = d_g + ((size_t)(b * NPIX + m)) * INTER;
        #pragma unroll
        for (int i = 0; i < INTER; i++)
            gp[i] = acc[i] + wgs[i * 128 + p];
    }
}

// ---------------- K5: f = Q Q^T via mma.sync bf16 hi/lo (3-term) ------------
// smem: double-buffered {Ahi, Alo, Bhi, Blo} tiles of 128 x 32 bf16, rows
// padded to 40 elems (80 B) -> row*80 mod 128 cycles through all 8 16B lanes,
// so ldmatrix 8-row phases are bank-conflict-free.
#define PADK 40
#define TILEB (128 * PADK * 2)   // 10240 B
#define BUFB  (4 * TILEB)        // 40960 B
#define G1_SMEM (2 * BUFB)       // 81920 B

__global__ __launch_bounds__(256, 2) void gemm1_mma() {
    extern __shared__ __align__(128) char smem[];
    uint32_t sb = smem_u32(smem);
    int t = threadIdx.x, wid = t >> 5, lane = t & 31;
    int p = blockIdx.x, b = blockIdx.y;
    int bi = 0;
    while (p >= NTILES - bi) { p -= NTILES - bi; bi++; }
    int bj = bi + p;
    int n0 = bi * 128, m0 = bj * 128;
    const __nv_bfloat16* qh = d_Qhi + (size_t)b * NPIX * KDIM;
    const __nv_bfloat16* ql = d_Qlo + (size_t)b * NPIX * KDIM;

    // per-thread load slots: 8 x 16B; tile = gi>>9 (0=Ahi,1=Alo,2=Bhi,3=Blo)
    int l_tile[8], l_row[8], l_seg[8];
    const __nv_bfloat16* l_src[8];
    #pragma unroll
    for (int j = 0; j < 8; j++) {
        int gi = j * 256 + t;
        int tile = gi >> 9;
        int s = gi & 511;
        l_tile[j] = tile;
        l_row[j] = s >> 2;
        l_seg[j] = s & 3;
        l_src[j] = (tile & 1) ? ql : qh;
    }

#define G1_ISSUE(kc) do { \
    uint32_t buf_ = sb + (uint32_t)((kc) & 1) * BUFB; \
    _Pragma("unroll") \
    for (int j = 0; j < 8; j++) { \
        int grow = ((l_tile[j] < 2) ? n0 : m0) + l_row[j]; \
        const __nv_bfloat16* g = l_src[j] + (size_t)grow * KDIM + (kc) * 32 + l_seg[j] * 8; \
        uint32_t saddr = buf_ + (uint32_t)(l_tile[j] * TILEB + l_row[j] * 80 + l_seg[j] * 16); \
        CPASYNC16(saddr, g); \
    } } while (0)

    G1_ISSUE(0); CPCOMMIT();
    G1_ISSUE(1); CPCOMMIT();

    int warp_m = wid & 1, warp_n = wid >> 1;   // 2 x 4 warp grid; warp tile 64m x 32n
    float c[16][4];
    #pragma unroll
    for (int q = 0; q < 16; q++) { c[q][0] = 0.f; c[q][1] = 0.f; c[q][2] = 0.f; c[q][3] = 0.f; }

    // ldmatrix lane-address components (constant across chunks)
    int a_row = warp_m * 64 + (lane & 15);       // + mf*16
    int a_col = (lane >> 4) * 8;                 // + ks*16
    int b_row = warp_n * 32 + ((lane & 7) | ((lane >> 4) << 3));  // + ng*16
    int b_col = ((lane >> 3) & 1) * 8;           // + ks*16

    const int termA[3] = {0, 0, 1};
    const int termB[3] = {2, 3, 2};

    for (int kc = 0; kc < NCHUNK; kc++) {
        CPWAIT1();
        __syncthreads();
        uint32_t buf = sb + (uint32_t)(kc & 1) * BUFB;
        #pragma unroll
        for (int term = 0; term < 3; term++) {
            uint32_t abase = buf + termA[term] * TILEB;
            uint32_t bbase = buf + termB[term] * TILEB;
            #pragma unroll
            for (int ks = 0; ks < 2; ks++) {
                uint32_t a[4][4], bfr[2][4];
                #pragma unroll
                for (int mf = 0; mf < 4; mf++) {
                    uint32_t addr = abase + (uint32_t)((a_row + mf * 16) * 80 + (a_col + ks * 16) * 2);
                    LDSM4(a[mf], addr);
                }
                #pragma unroll
                for (int ng = 0; ng < 2; ng++) {
                    uint32_t addr = bbase + (uint32_t)((b_row + ng * 16) * 80 + (b_col + ks * 16) * 2);
                    LDSM4(bfr[ng], addr);
                }
                #pragma unroll
                for (int mf = 0; mf < 4; mf++)
                    #pragma unroll
                    for (int nf = 0; nf < 4; nf++)
                        MMA16816(c[mf * 4 + nf], a[mf], &bfr[nf >> 1][(nf & 1) * 2]);
            }
        }
        __syncthreads();
        if (kc + 2 < NCHUNK) G1_ISSUE(kc + 2);
        CPCOMMIT();   // one group per iteration keeps wait_group accounting exact
    }

    // epilogue
    float* fb = d_f + (size_t)b * NPIX * NPIX;
    #pragma unroll
    for (int mf = 0; mf < 4; mf++) {
        int row0 = n0 + warp_m * 64 + mf * 16 + (lane >> 2);
        #pragma unroll
        for (int nf = 0; nf < 4; nf++) {
            int col = m0 + warp_n * 32 + nf * 8 + (lane & 3) * 2;
            float* cf = c[mf * 4 + nf];
            *(float2*)(fb + (size_t)row0 * NPIX + col)       = make_float2(cf[0], cf[1]);
            *(float2*)(fb + (size_t)(row0 + 8) * NPIX + col) = make_float2(cf[2], cf[3]);
        }
    }
    if (bi != bj) {
        #pragma unroll
        for (int mf = 0; mf < 4; mf++) {
            int row0 = n0 + warp_m * 64 + mf * 16 + (lane >> 2);
            #pragma unroll
            for (int nf = 0; nf < 4; nf++) {
                int col = m0 + warp_n * 32 + nf * 8 + (lane & 3) * 2;
                float* cf = c[mf * 4 + nf];
                fb[(size_t)col * NPIX + row0]           = cf[0];
                fb[(size_t)(col + 1) * NPIX + row0]     = cf[1];
                fb[(size_t)col * NPIX + row0 + 8]       = cf[2];
                fb[(size_t)(col + 1) * NPIX + row0 + 8] = cf[3];
            }
        }
    }
}

// ---------------- K6: per-row online max + sum(exp) -------------------------
__global__ void stats_kernel() {
    __shared__ float sm_m[8], sm_s[8];
    int b = blockIdx.y;
    int n = blockIdx.x;
    const float* row = d_f + ((size_t)(b * NPIX + n)) * NPIX;
    int t = threadIdx.x;
    float m = -1e30f, ssum = 0.f;
    for (int j = t; j < NPIX; j += 256) {
        float v = row[j];
        if (v > m) { ssum = ssum * __expf(m - v) + 1.f; m = v; }
        else ssum += __expf(v - m);
    }
    #pragma unroll
    for (int off = 16; off > 0; off >>= 1) {
        float m2 = __shfl_down_sync(0xffffffffu, m, off);
        float s2 = __shfl_down_sync(0xffffffffu, ssum, off);
        float mm = fmaxf(m, m2);
        ssum = ssum * __expf(m - mm) + s2 * __expf(m2 - mm);
        m = mm;
    }
    int w = t >> 5, lane = t & 31;
    if (lane == 0) { sm_m[w] = m; sm_s[w] = ssum; }
    __syncthreads();
    if (t == 0) {
        m = sm_m[0]; ssum = sm_s[0];
        #pragma unroll
        for (int i = 1; i < 8; i++) {
            float m2 = sm_m[i], s2 = sm_s[i];
            float mm = fmaxf(m, m2);
            ssum = ssum * __expf(m - mm) + s2 * __expf(m2 - mm);
            m = mm;
        }
        d_rowmax[b * NPIX + n] = m;
        d_rowsum[b * NPIX + n] = ssum;
    }
}

// ---------------- K7: y_part = exp(f - rowmax) @ g_x (K split x4) -----------
__global__ void gemm2_kernel() {
    __shared__ float Ps[64 * 64];
    __shared__ float Gs[64 * 32];
    int b = blockIdx.z;
    int ks = blockIdx.y;
    int n0 = blockIdx.x * 64;
    int t = threadIdx.x;
    int i = t & 31, rg = t >> 5;
    float acc[8] = {};
    const float* fb = d_f + (size_t)b * NPIX * NPIX;
    const float* gb = d_g + (size_t)b * NPIX * INTER;
    float rmax[16];
    #pragma unroll
    for (int j = 0; j < 16; j++)
        rmax[j] = d_rowmax[b * NPIX + n0 + (t >> 6) + 4 * j];
    for (int mc = ks * 1024; mc < ks * 1024 + 1024; mc += 64) {
        #pragma unroll
        for (int j = 0; j < 16; j++) {
            int idx = t + 256 * j;
            int row = (t >> 6) + 4 * j, m = idx & 63;
            float fv = fb[(size_t)(n0 + row) * NPIX + mc + m];
            Ps[idx] = __expf(fv - rmax[j]);
        }
        #pragma unroll
        for (int j = 0; j < 8; j++) {
            int idx = t + 256 * j;
            Gs[idx] = gb[(size_t)mc * INTER + idx];
        }
        __syncthreads();
        #pragma unroll 2
        for (int m = 0; m < 64; m += 4) {
            float g0 = Gs[(m + 0) * 32 + i];
            float g1 = Gs[(m + 1) * 32 + i];
            float g2 = Gs[(m + 2) * 32 + i];
            float g3 = Gs[(m + 3) * 32 + i];
            #pragma unroll
            for (int r = 0; r < 8; r++) {
                float4 pv = *(const float4*)(Ps + (rg * 8 + r) * 64 + m);
                acc[r] += pv.x * g0 + pv.y * g1 + pv.z * g2 + pv.w * g3;
            }
        }
        __syncthreads();
    }
    #pragma unroll
    for (int r = 0; r < 8; r++)
        d_ypart[(((size_t)ks * BATCH + b) * NPIX + n0 + rg * 8 + r) * INTER + i] = acc[r];
}

// ---------------- K8: z = Ww @ (sum ypart / rowsum) + x ----------------------
__global__ void zfinal_kernel(const float* __restrict__ x, const float* __restrict__ Ww,
                              float* __restrict__ z) {
    __shared__ float Wws[C1 * INTER];
    __shared__ float yt[64 * 33];
    int t = threadIdx.x;
    for (int j = t; j < C1 * INTER; j += 256) Wws[j] = Ww[j];
    int b = blockIdx.y;
    int hw0 = blockIdx.x * 64;
    #pragma unroll
    for (int j = 0; j < 8; j++) {
        int idx = t + 256 * j;
        int hwl = idx >> 5, i = idx & 31;
        int n = hw0 + hwl;
        float a = 0.f;
        #pragma unroll
        for (int ksp = 0; ksp < 4; ksp++)
            a += d_ypart[(((size_t)ksp * BATCH + b) * NPIX + n) * INTER + i];
        yt[hwl * 33 + i] = a / d_rowsum[b * NPIX + n];
    }
    __syncthreads();
    int hwl = t & 63, c0 = t >> 6;
    for (int c = c0; c < C1; c += 4) {
        float a = 0.f;
        #pragma unroll
        for (int i = 0; i < INTER; i++)
            a += Wws[c * INTER + i] * yt[hwl * 33 + i];
        size_t off = ((size_t)(b * C1 + c)) * NPIX + hw0 + hwl;
        z[off] = a + x[off];
    }
}

// ---------------- launch -----------------------------------------------------
extern "C" void kernel_launch(void* const* d_in, const int* in_sizes, int n_in,
                              void* d_out, int out_size) {
    const float* x  = (const float*)d_in[0];
    const float* Wg = (const float*)d_in[1];
    const float* Ww = (const float*)d_in[2];
    const float* W1 = (const float*)d_in[3];
    const float* W2 = (const float*)d_in[4];
    float* z = (float*)d_out;

    static int init = 0;
    if (!init) {
        cudaFuncSetAttribute(gemm1_mma, cudaFuncAttributeMaxDynamicSharedMemorySize, G1_SMEM);
        init = 1;
    }

    pool_kernel<<<BATCH * C1, 256>>>(x);
    vcalc_kernel<<<1, 192>>>(W1, W2);
    buildq_kernel<<<dim3(128, 24, BATCH), dim3(32, 8)>>>(x);
    gx_kernel<<<dim3(32, BATCH), 256>>>(x, Wg);
    gemm1_mma<<<dim3(NPAIRS, BATCH), 256, G1_SMEM>>>();
    stats_kernel<<<dim3(NPIX, BATCH), 256>>>();
    gemm2_kernel<<<dim3(64, 4, BATCH), 256>>>();
    zfinal_kernel<<<dim3(64, BATCH), 256>>>(x, Ww, z);
}